// round 8
// baseline (speedup 1.0000x reference)
#include <cuda_runtime.h>
#include <cuda_bf16.h>

// PatternAwareLoss: mean over (B,S,L) of boost*mask*(softplus(x) - x*y) / sum(mask)
// B=64, S=8192, L=24. boost[b,s]=1.2 if any-label(s) && any-label(s+1) && s<S-1.
//
// R6: element-parallel layout. Thread = 4 consecutive elems (float4/int4,
// perfectly coalesced LDG.128; 4|24 so each quad is inside one position).
// Per-thread partials (relu-sum, prod(1+e^-|x|), label-OR) -> smem; 64
// combine threads fold 6 partials/position, 1 LG2/position, boost from
// neighbor ORs (halo for tile edge). Persistent 592-block grid (4/SM, one
// wave), ticket last-block finish (592 partials, ~free tail).

#define L_DIM  24
#define S_LEN  8192
#define NPOS   (64 * 8192)
#define POST   64                  // positions per tile
#define TPB    384                 // threads per block = POST*6
#define NTILE  (NPOS / POST)       // 8192
#define GRID   592                 // 4 blocks/SM * 148, single wave

__device__ float2       g_part[GRID];
__device__ unsigned int g_ticket = 0;   // self-resetting

__global__ __launch_bounds__(TPB) void loss_kernel(
    const float4* __restrict__ lg4,
    const int4*   __restrict__ lb4,
    const float*  __restrict__ amask,
    float*        __restrict__ out)
{
    __shared__ float    s_sm[TPB];
    __shared__ float    s_lp[TPB];
    __shared__ unsigned s_or[TPB];
    __shared__ unsigned s_halo;
    __shared__ bool     s_last;
    __shared__ double   sn[TPB];
    __shared__ double   sd[TPB];

    const int t = threadIdx.x;
    float accn = 0.f, accd = 0.f;   // meaningful for t < POST

    for (int tile = blockIdx.x; tile < NTILE; tile += GRID) {
        const size_t q = (size_t)tile * TPB + t;    // float4 index
        float4 x = lg4[q];
        int4   y = lb4[q];

        float mreg = 0.f;
        if (t < POST) mreg = amask[tile * POST + t];

        if (t == 0) {                               // halo: next tile's first position
            unsigned h = 0;
            int np = (tile + 1) * POST;
            if ((np & (S_LEN - 1)) != 0) {          // same sequence (also guards OOB)
                const int4* nb = lb4 + (size_t)np * (L_DIM / 4);
#pragma unroll
                for (int i = 0; i < L_DIM / 4; i++) {
                    int4 v = nb[i];
                    h |= (unsigned)(v.x | v.y | v.z | v.w);
                }
            }
            s_halo = h;
        }

        // elementwise: relu part + product of (1 + exp(-|x|))
        float sm = 0.f, pp = 1.f;
        {
            float r, u;
            r = y.x ? fmaxf(-x.x, 0.f) : fmaxf(x.x, 0.f); sm += r;
            u = __expf(-fabsf(x.x)); pp = fmaf(pp, u, pp);
            r = y.y ? fmaxf(-x.y, 0.f) : fmaxf(x.y, 0.f); sm += r;
            u = __expf(-fabsf(x.y)); pp = fmaf(pp, u, pp);
            r = y.z ? fmaxf(-x.z, 0.f) : fmaxf(x.z, 0.f); sm += r;
            u = __expf(-fabsf(x.z)); pp = fmaf(pp, u, pp);
            r = y.w ? fmaxf(-x.w, 0.f) : fmaxf(x.w, 0.f); sm += r;
            u = __expf(-fabsf(x.w)); pp = fmaf(pp, u, pp);
        }
        s_sm[t] = sm;
        s_lp[t] = pp;
        s_or[t] = (unsigned)(y.x | y.y | y.z | y.w);
        __syncthreads();

        if (t < POST) {                             // one combine thread per position
            const int b = 6 * t;
            float sm6 = ((s_sm[b] + s_sm[b+1]) + (s_sm[b+2] + s_sm[b+3])) + (s_sm[b+4] + s_sm[b+5]);
            float lp6 = ((s_lp[b] * s_lp[b+1]) * (s_lp[b+2] * s_lp[b+3])) * (s_lp[b+4] * s_lp[b+5]);
            unsigned o6  = s_or[b] | s_or[b+1] | s_or[b+2] | s_or[b+3] | s_or[b+4] | s_or[b+5];
            unsigned on6 = (t < POST - 1)
                ? (s_or[b+6] | s_or[b+7] | s_or[b+8] | s_or[b+9] | s_or[b+10] | s_or[b+11])
                : s_halo;
            // possum = sum(relu - x*y) + ln2 * log2(prod(1+e^-|x|))
            float possum = fmaf(0.69314718055994531f, __log2f(lp6), sm6);
            int pos = tile * POST + t;
            float boost = (((pos & (S_LEN - 1)) != S_LEN - 1) && o6 && on6) ? 1.2f : 1.0f;
            accn = fmaf(mreg * boost, possum, accn);
            accd += mreg;
        }
        __syncthreads();                            // smem reuse next tile
    }

    // ── block reduce over the 64 combine-thread accumulators ──
    if (t < POST) { s_sm[t] = accn; s_lp[t] = accd; }
    __syncthreads();
    if (t < 32) {
        float n = s_sm[t] + s_sm[t + 32];
        float d = s_lp[t] + s_lp[t + 32];
#pragma unroll
        for (int off = 16; off > 0; off >>= 1) {
            n += __shfl_down_sync(0xffffffffu, n, off);
            d += __shfl_down_sync(0xffffffffu, d, off);
        }
        if (t == 0) {
            g_part[blockIdx.x] = make_float2(n, d);
            __threadfence();                        // partial visible before ticket
            unsigned tk = atomicAdd(&g_ticket, 1u);
            s_last = (tk == (unsigned)(GRID - 1));
        }
    }
    __syncthreads();
    if (!s_last) return;

    // ── last block: final reduction over GRID partials (L2-resident) ──
    __threadfence();                                // acquire
    double n = 0.0, d = 0.0;
    for (int i = t; i < GRID; i += TPB) {
        float2 v = g_part[i];
        n += (double)v.x;
        d += (double)v.y;
    }
    sn[t] = n;
    sd[t] = d;
    __syncthreads();
#pragma unroll
    for (int s = TPB / 2; s >= 3; s >>= 1) {        // 192,96,48,24,12,6,3
        if (t < s) { sn[t] += sn[t + s]; sd[t] += sd[t + s]; }
        __syncthreads();
    }
    if (t == 0) {
        out[0] = (float)((sn[0] + sn[1] + sn[2]) / (sd[0] + sd[1] + sd[2]));
        g_ticket = 0;                               // reset for next graph replay
    }
}

extern "C" void kernel_launch(void* const* d_in, const int* in_sizes, int n_in,
                              void* d_out, int out_size)
{
    const float4* lg4  = (const float4*)d_in[0];
    const int4*   lb4  = (const int4*)d_in[1];
    const float*  mask = (const float*)d_in[2];
    float* out = (float*)d_out;

    loss_kernel<<<GRID, TPB>>>(lg4, lb4, mask, out);
}

// round 14
// speedup vs baseline: 1.0756x; 1.0756x over previous
#include <cuda_runtime.h>
#include <cuda_bf16.h>

// PatternAwareLoss: mean over (B,S,L) of boost*mask*(softplus(x) - x*y) / sum(mask)
// B=64, S=8192, L=24. boost[b,s]=1.2 if any-label(s) && any-label(s+1) && s<S-1.
//
// R14 == R12 resubmitted (R13 was a container infra failure; kernel unmeasured).
// Barrier-free warp-ballot layout with fixed normalization (reference
// denominator is Sum(mask) over [B,S,1]; R11 returned exactly ref/24, proving
// the compute path bit-correct). Warp owns 16 positions/round (96 quads, 3
// coalesced slots of 32 float4/int4). Per-quad label-ORs -> 3 ballots -> a
// uniform 96-bit has-punct bitmap; boost extracted locally by shifts. One LG2
// per quad via prod(1+e^-|x|). Position 15's contribution deferred one round.
// No smem / no __syncthreads in the main loop -> loads stay in flight.
// 512 blocks x 8 warps x 128-position spans; ticket last-block finish.

#define S_LEN   8192
#define NPOS    (64 * 8192)
#define TPB     256
#define WPB     8                   // warps per block
#define GRID    512
#define SPAN    128                 // positions per warp
#define ROUNDS  (SPAN / 16)         // 8
#define LN2     0.69314718055994531f

__device__ float2       g_part[GRID];
__device__ unsigned int g_ticket = 0;   // self-resetting

// per-quad: relu-part sum and product of (1+exp(-|x|))
__device__ __forceinline__ void quad_core(const float4& x, const int4& y,
                                          float& sm, float& pp) {
    float r, u;
    sm = 0.f; pp = 1.f;
    r = y.x ? fmaxf(-x.x, 0.f) : fmaxf(x.x, 0.f); sm += r;
    u = __expf(-fabsf(x.x)); pp = fmaf(pp, u, pp);
    r = y.y ? fmaxf(-x.y, 0.f) : fmaxf(x.y, 0.f); sm += r;
    u = __expf(-fabsf(x.y)); pp = fmaf(pp, u, pp);
    r = y.z ? fmaxf(-x.z, 0.f) : fmaxf(x.z, 0.f); sm += r;
    u = __expf(-fabsf(x.z)); pp = fmaf(pp, u, pp);
    r = y.w ? fmaxf(-x.w, 0.f) : fmaxf(x.w, 0.f); sm += r;
    u = __expf(-fabsf(x.w)); pp = fmaf(pp, u, pp);
}

// has_punct of local position p (0..15) from the uniform 96-bit bitmap (lo, hi)
__device__ __forceinline__ bool orb(unsigned long long lo, unsigned long long hi, int p) {
    unsigned long long w = (p < 10) ? (lo >> (6 * p)) : (hi >> (6 * p - 60));
    return (w & 63ull) != 0ull;
}

__global__ __launch_bounds__(TPB) void loss_kernel(
    const float4* __restrict__ lg4,
    const int4*   __restrict__ lb4,
    const float*  __restrict__ amask,
    float*        __restrict__ out)
{
    const int t    = threadIdx.x;
    const int lane = t & 31;
    const int wg   = blockIdx.x * WPB + (t >> 5);      // global warp id
    const size_t pbase = (size_t)wg * SPAN;

    // lane -> local position per slot (constant per thread)
    const int p0 = lane / 6;                            // 0..5
    const int p1 = (lane + 32) / 6;                     // 5..10
    const int p2 = (lane + 64) / 6;                     // 10..15

    float accn = 0.f, accd = 0.f;
    float defer = 0.f;                                  // pos-15 pending contribution
    bool  or15_prev = false;

#pragma unroll 2
    for (int r = 0; r < ROUNDS; r++) {
        const size_t pos0 = pbase + (size_t)r * 16;
        const size_t q0   = pos0 * 6;

        // ── 6 independent coalesced LDG.128 ──
        float4 x0 = lg4[q0 + lane];
        float4 x1 = lg4[q0 + 32 + lane];
        float4 x2 = lg4[q0 + 64 + lane];
        int4   y0 = lb4[q0 + lane];
        int4   y1 = lb4[q0 + 32 + lane];
        int4   y2 = lb4[q0 + 64 + lane];
        float  m0 = amask[pos0 + p0];
        float  m1 = amask[pos0 + p1];
        float  m2 = amask[pos0 + p2];

        // ── uniform 96-bit per-quad-OR bitmap via ballots ──
        unsigned o0 = (unsigned)(y0.x | y0.y | y0.z | y0.w);
        unsigned o1 = (unsigned)(y1.x | y1.y | y1.z | y1.w);
        unsigned o2 = (unsigned)(y2.x | y2.y | y2.z | y2.w);
        unsigned b0 = __ballot_sync(0xffffffffu, o0 != 0);
        unsigned b1 = __ballot_sync(0xffffffffu, o1 != 0);
        unsigned b2 = __ballot_sync(0xffffffffu, o2 != 0);
        unsigned long long lo = (unsigned long long)b0 | ((unsigned long long)b1 << 32);
        unsigned long long hi = (lo >> 60) | ((unsigned long long)b2 << 4); // quads 60..95

        // resolve previous round's deferred pos-15 (its p+1 is our local p=0)
        {
            float bf = (or15_prev && ((lo & 63ull) != 0ull)) ? 1.2f : 1.0f;
            accn = fmaf(defer, bf, accn);
            defer = 0.f;
        }

        // ── per-quad compute; boost from bitmap; pos 15 deferred ──
        float sm, pp, possum, bf;

        quad_core(x0, y0, sm, pp);
        possum = fmaf(LN2, __log2f(pp), sm);
        bf = (orb(lo, hi, p0) && orb(lo, hi, p0 + 1)) ? 1.2f : 1.0f;  // p0<=5, never 15
        accn = fmaf(m0 * bf, possum, accn);
        accd += m0;

        quad_core(x1, y1, sm, pp);
        possum = fmaf(LN2, __log2f(pp), sm);
        bf = (orb(lo, hi, p1) && orb(lo, hi, p1 + 1)) ? 1.2f : 1.0f;  // p1<=10, never 15
        accn = fmaf(m1 * bf, possum, accn);
        accd += m1;

        quad_core(x2, y2, sm, pp);
        possum = fmaf(LN2, __log2f(pp), sm);
        if (p2 == 15) {
            defer += m2 * possum;                       // boost resolved next round
        } else {
            bf = (orb(lo, hi, p2) && orb(lo, hi, p2 + 1)) ? 1.2f : 1.0f;
            accn = fmaf(m2 * bf, possum, accn);
        }
        accd += m2;

        or15_prev = ((hi >> 30) & 63ull) != 0ull;
    }

    // ── resolve final deferred position (last of the warp's span) ──
    {
        const size_t plast = pbase + SPAN - 1;
        float bf = 1.0f;                                // s == S-1: never boosted
        if ((plast & (size_t)(S_LEN - 1)) != (size_t)(S_LEN - 1)) {
            int ho = 0;
            if (lane < 6) {
                int4 v = lb4[(pbase + SPAN) * 6 + lane];
                ho = v.x | v.y | v.z | v.w;
            }
            unsigned hb = __ballot_sync(0xffffffffu, ho != 0);
            bf = (or15_prev && ((hb & 63u) != 0u)) ? 1.2f : 1.0f;
        }
        accn = fmaf(defer, bf, accn);
    }

    // ── block reduction (shfl + tiny smem) ──
#pragma unroll
    for (int off = 16; off > 0; off >>= 1) {
        accn += __shfl_down_sync(0xffffffffu, accn, off);
        accd += __shfl_down_sync(0xffffffffu, accd, off);
    }
    __shared__ float2 wsum[WPB];
    __shared__ bool   s_last;
    if (lane == 0) wsum[t >> 5] = make_float2(accn, accd);
    __syncthreads();
    if (t == 0) {
        float n = 0.f, d = 0.f;
#pragma unroll
        for (int i = 0; i < WPB; i++) { n += wsum[i].x; d += wsum[i].y; }
        g_part[blockIdx.x] = make_float2(n, d);
        __threadfence();
        unsigned tk = atomicAdd(&g_ticket, 1u);
        s_last = (tk == (unsigned)(GRID - 1));
    }
    __syncthreads();
    if (!s_last) return;

    // ── last block: final reduce over GRID partials (L2-resident) ──
    __threadfence();                                    // acquire
    double n = 0.0, d = 0.0;
    for (int i = t; i < GRID; i += TPB) {               // 2 loads/thread
        float2 v = g_part[i];
        n += (double)v.x;
        d += (double)v.y;
    }
    __shared__ double sn[TPB];
    __shared__ double sd[TPB];
    sn[t] = n;
    sd[t] = d;
    __syncthreads();
#pragma unroll
    for (int s = TPB / 2; s > 0; s >>= 1) {
        if (t < s) { sn[t] += sn[t + s]; sd[t] += sd[t + s]; }
        __syncthreads();
    }
    if (t == 0) {
        // accd summed one m per quad over 6 quads/position = 6*Sum(m);
        // reference denominator is Sum(m) (mask shape [B,S,1]) -> out = 6*n/d.
        out[0] = (float)(6.0 * sn[0] / sd[0]);
        g_ticket = 0;                                   // reset for next graph replay
    }
}

extern "C" void kernel_launch(void* const* d_in, const int* in_sizes, int n_in,
                              void* d_out, int out_size)
{
    const float4* lg4  = (const float4*)d_in[0];
    const int4*   lb4  = (const int4*)d_in[1];
    const float*  mask = (const float*)d_in[2];
    float* out = (float*)d_out;

    loss_kernel<<<GRID, TPB>>>(lg4, lb4, mask, out);
}

// round 15
// speedup vs baseline: 1.2531x; 1.1650x over previous
#include <cuda_runtime.h>
#include <cuda_bf16.h>

// PatternAwareLoss: mean over (B,S,L) of boost*mask*(softplus(x) - x*y) / sum(mask)
// B=64, S=8192, L=24. boost[b,s]=1.2 if any-label(s) && any-label(s+1) && s<S-1.
//
// R15: R14 + explicit software pipelining. In R14 every round's ballot chain
// required that round's label loads before any accumulation -> effective
// pipeline depth ~1 round -> ~1 load in flight per warp -> BW capped ~4TB/s
// regardless of occupancy (42% vs 71% made no difference). Now iteration r
// issues tile r+1's loads first, then ballots/computes on tile r's registers
// (loaded one full iteration earlier -> DRAM latency covered by compute).
// The loop epilogue's "next" registers are exactly the halo tile, so the
// special halo load is gone. Normalization: denominator is Sum(mask) over
// [B,S,1]; accd accumulates 6 m per position -> out = 6*n/d (verified R14).

#define S_LEN   8192
#define NPOS    (64 * 8192)
#define TPB     256
#define WPB     8                   // warps per block
#define GRID    512
#define SPAN    128                 // positions per warp
#define ROUNDS  (SPAN / 16)         // 8
#define LN2     0.69314718055994531f

__device__ float2       g_part[GRID];
__device__ unsigned int g_ticket = 0;   // self-resetting

// per-quad: relu-part sum and product of (1+exp(-|x|))
__device__ __forceinline__ void quad_core(const float4& x, const int4& y,
                                          float& sm, float& pp) {
    float r, u;
    sm = 0.f; pp = 1.f;
    r = y.x ? fmaxf(-x.x, 0.f) : fmaxf(x.x, 0.f); sm += r;
    u = __expf(-fabsf(x.x)); pp = fmaf(pp, u, pp);
    r = y.y ? fmaxf(-x.y, 0.f) : fmaxf(x.y, 0.f); sm += r;
    u = __expf(-fabsf(x.y)); pp = fmaf(pp, u, pp);
    r = y.z ? fmaxf(-x.z, 0.f) : fmaxf(x.z, 0.f); sm += r;
    u = __expf(-fabsf(x.z)); pp = fmaf(pp, u, pp);
    r = y.w ? fmaxf(-x.w, 0.f) : fmaxf(x.w, 0.f); sm += r;
    u = __expf(-fabsf(x.w)); pp = fmaf(pp, u, pp);
}

// has_punct of local position p (0..15) from the uniform 96-bit bitmap (lo, hi)
__device__ __forceinline__ bool orb(unsigned long long lo, unsigned long long hi, int p) {
    unsigned long long w = (p < 10) ? (lo >> (6 * p)) : (hi >> (6 * p - 60));
    return (w & 63ull) != 0ull;
}

__global__ __launch_bounds__(TPB) void loss_kernel(
    const float4* __restrict__ lg4,
    const int4*   __restrict__ lb4,
    const float*  __restrict__ amask,
    float*        __restrict__ out)
{
    const int t    = threadIdx.x;
    const int lane = t & 31;
    const int wg   = blockIdx.x * WPB + (t >> 5);      // global warp id
    const size_t pbase = (size_t)wg * SPAN;

    // lane -> local position per slot (constant per thread)
    const int p0 = lane / 6;                            // 0..5
    const int p1 = (lane + 32) / 6;                     // 5..10
    const int p2 = (lane + 64) / 6;                     // 10..15

    float accn = 0.f, accd = 0.f;
    float defer = 0.f;                                  // pos-15 pending contribution
    bool  or15_prev = false;

    // ── prologue: load tile 0 ──
    float4 xc0, xc1, xc2;  int4 yc0, yc1, yc2;  float mc0, mc1, mc2;
    {
        const size_t q0 = pbase * 6;
        xc0 = lg4[q0 + lane]; xc1 = lg4[q0 + 32 + lane]; xc2 = lg4[q0 + 64 + lane];
        yc0 = lb4[q0 + lane]; yc1 = lb4[q0 + 32 + lane]; yc2 = lb4[q0 + 64 + lane];
        mc0 = amask[pbase + p0]; mc1 = amask[pbase + p1]; mc2 = amask[pbase + p2];
    }

#pragma unroll 2
    for (int r = 0; r < ROUNDS; r++) {
        const size_t pos0 = pbase + (size_t)r * 16;

        // ── issue NEXT tile's loads first (latency covered by this round) ──
        const size_t npos0 = pos0 + 16;
        const size_t nbase = (npos0 < (size_t)NPOS) ? npos0 : 0;   // clamp last warp
        const size_t nq0   = nbase * 6;
        float4 xn0 = lg4[nq0 + lane];
        float4 xn1 = lg4[nq0 + 32 + lane];
        float4 xn2 = lg4[nq0 + 64 + lane];
        int4   yn0 = lb4[nq0 + lane];
        int4   yn1 = lb4[nq0 + 32 + lane];
        int4   yn2 = lb4[nq0 + 64 + lane];
        float  mn0 = amask[nbase + p0];
        float  mn1 = amask[nbase + p1];
        float  mn2 = amask[nbase + p2];

        // ── ballots on CURRENT labels (arrived one iteration ago) ──
        unsigned o0 = (unsigned)(yc0.x | yc0.y | yc0.z | yc0.w);
        unsigned o1 = (unsigned)(yc1.x | yc1.y | yc1.z | yc1.w);
        unsigned o2 = (unsigned)(yc2.x | yc2.y | yc2.z | yc2.w);
        unsigned b0 = __ballot_sync(0xffffffffu, o0 != 0);
        unsigned b1 = __ballot_sync(0xffffffffu, o1 != 0);
        unsigned b2 = __ballot_sync(0xffffffffu, o2 != 0);
        unsigned long long lo = (unsigned long long)b0 | ((unsigned long long)b1 << 32);
        unsigned long long hi = (lo >> 60) | ((unsigned long long)b2 << 4); // quads 60..95

        // resolve previous round's deferred pos-15 (its p+1 is our local p=0)
        {
            float bf = (or15_prev && ((lo & 63ull) != 0ull)) ? 1.2f : 1.0f;
            accn = fmaf(defer, bf, accn);
            defer = 0.f;
        }

        // ── per-quad compute on CURRENT tile; pos 15 deferred ──
        float sm, pp, possum, bf;

        quad_core(xc0, yc0, sm, pp);
        possum = fmaf(LN2, __log2f(pp), sm);
        bf = (orb(lo, hi, p0) && orb(lo, hi, p0 + 1)) ? 1.2f : 1.0f;  // p0<=5, never 15
        accn = fmaf(mc0 * bf, possum, accn);
        accd += mc0;

        quad_core(xc1, yc1, sm, pp);
        possum = fmaf(LN2, __log2f(pp), sm);
        bf = (orb(lo, hi, p1) && orb(lo, hi, p1 + 1)) ? 1.2f : 1.0f;  // p1<=10, never 15
        accn = fmaf(mc1 * bf, possum, accn);
        accd += mc1;

        quad_core(xc2, yc2, sm, pp);
        possum = fmaf(LN2, __log2f(pp), sm);
        if (p2 == 15) {
            defer += mc2 * possum;                      // boost resolved next round
        } else {
            bf = (orb(lo, hi, p2) && orb(lo, hi, p2 + 1)) ? 1.2f : 1.0f;
            accn = fmaf(mc2 * bf, possum, accn);
        }
        accd += mc2;

        or15_prev = ((hi >> 30) & 63ull) != 0ull;

        // ── rotate: next becomes current ──
        xc0 = xn0; xc1 = xn1; xc2 = xn2;
        yc0 = yn0; yc1 = yn1; yc2 = yn2;
        mc0 = mn0; mc1 = mn1; mc2 = mn2;
    }

    // ── epilogue: cur now holds the halo tile (first tile after the span) ──
    {
        const size_t plast = pbase + SPAN - 1;
        unsigned hb = __ballot_sync(0xffffffffu,
                                    (yc0.x | yc0.y | yc0.z | yc0.w) != 0);
        // hp of position pbase+SPAN = quads 0..5 = lanes 0..5 of slot 0
        float bf = 1.0f;                                // s == S-1: never boosted
        if (((plast & (size_t)(S_LEN - 1)) != (size_t)(S_LEN - 1))
            && or15_prev && ((hb & 63u) != 0u))
            bf = 1.2f;
        accn = fmaf(defer, bf, accn);
    }

    // ── block reduction (shfl + tiny smem) ──
#pragma unroll
    for (int off = 16; off > 0; off >>= 1) {
        accn += __shfl_down_sync(0xffffffffu, accn, off);
        accd += __shfl_down_sync(0xffffffffu, accd, off);
    }
    __shared__ float2 wsum[WPB];
    __shared__ bool   s_last;
    if (lane == 0) wsum[t >> 5] = make_float2(accn, accd);
    __syncthreads();
    if (t == 0) {
        float n = 0.f, d = 0.f;
#pragma unroll
        for (int i = 0; i < WPB; i++) { n += wsum[i].x; d += wsum[i].y; }
        g_part[blockIdx.x] = make_float2(n, d);
        __threadfence();
        unsigned tk = atomicAdd(&g_ticket, 1u);
        s_last = (tk == (unsigned)(GRID - 1));
    }
    __syncthreads();
    if (!s_last) return;

    // ── last block: final reduce over GRID partials (L2-resident) ──
    __threadfence();                                    // acquire
    double n = 0.0, d = 0.0;
    for (int i = t; i < GRID; i += TPB) {               // 2 loads/thread
        float2 v = g_part[i];
        n += (double)v.x;
        d += (double)v.y;
    }
    __shared__ double sn[TPB];
    __shared__ double sd[TPB];
    sn[t] = n;
    sd[t] = d;
    __syncthreads();
#pragma unroll
    for (int s = TPB / 2; s > 0; s >>= 1) {
        if (t < s) { sn[t] += sn[t + s]; sd[t] += sd[t + s]; }
        __syncthreads();
    }
    if (t == 0) {
        // accd = 6*Sum(m); reference denominator is Sum(m) -> out = 6*n/d.
        out[0] = (float)(6.0 * sn[0] / sd[0]);
        g_ticket = 0;                                   // reset for next graph replay
    }
}

extern "C" void kernel_launch(void* const* d_in, const int* in_sizes, int n_in,
                              void* d_out, int out_size)
{
    const float4* lg4  = (const float4*)d_in[0];
    const int4*   lb4  = (const int4*)d_in[1];
    const float*  mask = (const float*)d_in[2];
    float* out = (float*)d_out;

    loss_kernel<<<GRID, TPB>>>(lg4, lb4, mask, out);
}